// round 6
// baseline (speedup 1.0000x reference)
#include <cuda_runtime.h>
#include <cuda_bf16.h>
#include <stdint.h>

#define EN    1024
#define ED    64
#define SP    32768
#define NPOS  131072
#define CTAM  256
#define NCTA  (NPOS / CTAM)     // 512
#define CHN   128
#define NCH   8
#define RS    68                // smem row stride in u32 words (272B) -> conflict-free
#define MARGIN 3.5e-4f

// smem layout (u32 word offsets)
#define W_SN    0                       // 1024 floats (all code norms)
#define W_STAGE 1024                    // 256 x RS words (A: [x_hi|x_lo] bf16 pairs)
#define W_B0    (W_STAGE + 256 * RS)    // B chunk buf 0: 128 x RS
#define W_B1    (W_B0 + 128 * RS)
#define SMEM_WORDS (W_B1 + 128 * RS)
#define SMEM_BYTES (SMEM_WORDS * 4)     // 143360

__device__ float    g_norms[EN];
__device__ unsigned g_ebf[EN * 64];     // bf16x2 rows: [e_hi(64) | e_hi(64)]
__device__ uint2    g_top[NPOS];
__device__ unsigned g_flagcnt;
__device__ unsigned g_flaglist[NPOS];

// ---------------- helpers ----------------
__device__ __forceinline__ unsigned sptr(const void* p) {
    return (unsigned)__cvta_generic_to_shared(p);
}
__device__ __forceinline__ unsigned bhi(float f) {
    return (unsigned)__bfloat16_as_ushort(__float2bfloat16(f));
}
#define CP16(d, s)  asm volatile("cp.async.cg.shared.global [%0], [%1], 16;" :: "r"(d), "l"(s) : "memory")
#define CP_COMMIT() asm volatile("cp.async.commit_group;" ::: "memory")
#define CP_WAIT1()  asm volatile("cp.async.wait_group 1;" ::: "memory")
#define CP_WAIT0()  asm volatile("cp.async.wait_group 0;" ::: "memory")

#define MMA(c, a, b0, b1) asm volatile( \
    "mma.sync.aligned.m16n8k16.row.col.f32.bf16.bf16.f32 " \
    "{%0,%1,%2,%3}, {%4,%5,%6,%7}, {%8,%9}, {%0,%1,%2,%3};" \
    : "+f"((c)[0]), "+f"((c)[1]), "+f"((c)[2]), "+f"((c)[3]) \
    : "r"((a)[0]), "r"((a)[1]), "r"((a)[2]), "r"((a)[3]), "r"(b0), "r"(b1))

struct Trk { float v1, v2, v3; int i1, i2; };
__device__ __forceinline__ void upd(Trk& t, float d, int col) {
    if (d < t.v1)      { t.v3 = t.v2; t.v2 = t.v1; t.i2 = t.i1; t.v1 = d; t.i1 = col; }
    else if (d < t.v2) { t.v3 = t.v2; t.v2 = d; t.i2 = col; }
    else if (d < t.v3) { t.v3 = d; }
}

// ---------------- K1: norms + flag reset ----------------
__global__ void vq_norms_kernel(const float* __restrict__ emb) {
    if (blockIdx.x == 0 && threadIdx.x == 0) g_flagcnt = 0;
    int j = blockIdx.x * blockDim.x + threadIdx.x;
    if (j < EN) {
        const float4* row = (const float4*)(emb + j * ED);
        float s = 0.f;
#pragma unroll
        for (int k = 0; k < ED / 4; k++) {
            float4 v = row[k];
            s += v.x * v.x + v.y * v.y + v.z * v.z + v.w * v.w;
        }
        g_norms[j] = s;
    }
}

// ---------------- K2: codebook -> bf16x2 image rows [e_hi | e_hi] ----------------
__global__ __launch_bounds__(256) void vq_ebuild_kernel(const float* __restrict__ emb) {
    int idx = blockIdx.x * 256 + threadIdx.x;    // 0 .. 65535
    int j = idx >> 6, w = idx & 63;
    int qq = (w < 32) ? w : (w - 32);
    float f0 = emb[j * ED + 2 * qq];
    float f1 = emb[j * ED + 2 * qq + 1];
    g_ebf[idx] = bhi(f0) | (bhi(f1) << 16);
}

// ---------------- K3: mma.sync GEMM + top2/top3 shortlist ----------------
__global__ __launch_bounds__(256, 1) void vq_gemm_kernel(const float* __restrict__ z) {
    extern __shared__ unsigned sm[];
    float*    snf   = (float*)(sm + W_SN);
    unsigned* stage = sm + W_STAGE;
    const int tid = threadIdx.x, w = tid >> 5, l = tid & 31;
    const int q = l >> 2, r = l & 3;

    // group0: all norms (4KB) + B chunk 0
    CP16(sptr(sm + W_SN) + tid * 16, (const char*)g_norms + tid * 16);
    {
        const char* src = (const char*)g_ebf;
        unsigned b = sptr(sm + W_B0);
#pragma unroll
        for (int i = 0; i < 8; i++) {
            int e = tid + i * 256, row = e >> 4, seg = e & 15;
            CP16(b + row * 272 + seg * 16, src + row * 256 + seg * 16);
        }
    }
    CP_COMMIT();

    // stage A = [x_hi | x_lo] bf16 pairs, row = CTA-local position
    const int p0 = blockIdx.x * CTAM;
    const float* zb = z + (p0 >> 15) * (ED * SP) + (p0 & (SP - 1));
#pragma unroll
    for (int qq = 0; qq < 32; qq++) {
        float f0 = zb[(2 * qq) * SP + tid];
        float f1 = zb[(2 * qq + 1) * SP + tid];
        float g0 = __bfloat162float(__float2bfloat16(f0));
        float g1 = __bfloat162float(__float2bfloat16(f1));
        stage[tid * RS + qq]      = bhi(f0) | (bhi(f1) << 16);
        stage[tid * RS + 32 + qq] = bhi(__fsub_rn(f0, g0)) | (bhi(__fsub_rn(f1, g1)) << 16);
    }
    __syncthreads();

    // resident A fragments: 2 m-tiles x 8 k-steps x 4 regs
    unsigned A[2][8][4];
    const int W0 = w * 32;
#pragma unroll
    for (int m = 0; m < 2; m++)
#pragma unroll
        for (int s = 0; s < 8; s++) {
            int base = (W0 + m * 16 + q) * RS + s * 8 + r;
            A[m][s][0] = stage[base];
            A[m][s][1] = stage[base + 8 * RS];
            A[m][s][2] = stage[base + 4];
            A[m][s][3] = stage[base + 8 * RS + 4];
        }

    Trk trk[2][2];
#pragma unroll
    for (int m = 0; m < 2; m++)
#pragma unroll
        for (int h = 0; h < 2; h++)
            trk[m][h] = Trk{3.4e38f, 3.4e38f, 3.4e38f, 0, 0};

#pragma unroll 1
    for (int c = 0; c < NCH; c++) {
        if (c < NCH - 1) {                       // prefetch next chunk
            const char* src = (const char*)g_ebf + (c + 1) * CHN * 256;
            unsigned b = sptr(sm + (((c + 1) & 1) ? W_B1 : W_B0));
#pragma unroll
            for (int i = 0; i < 8; i++) {
                int e = tid + i * 256, row = e >> 4, seg = e & 15;
                CP16(b + row * 272 + seg * 16, src + row * 256 + seg * 16);
            }
            CP_COMMIT();
            CP_WAIT1();
        } else {
            CP_WAIT0();
        }
        __syncthreads();
        const unsigned* bb = sm + ((c & 1) ? W_B1 : W_B0);

#pragma unroll 1
        for (int nb = 0; nb < 2; nb++) {         // two 64-code blocks per chunk
            float acc[8][2][4];
#pragma unroll
            for (int nt = 0; nt < 8; nt++)
#pragma unroll
                for (int m = 0; m < 2; m++)
#pragma unroll
                    for (int k = 0; k < 4; k++) acc[nt][m][k] = 0.f;
#pragma unroll
            for (int s = 0; s < 8; s++)
#pragma unroll
                for (int nt = 0; nt < 8; nt++) {
                    int bw = (nb * 64 + nt * 8 + q) * RS + s * 8 + r;
                    unsigned b0 = bb[bw], b1 = bb[bw + 4];
                    MMA(acc[nt][0], A[0][s], b0, b1);
                    MMA(acc[nt][1], A[1][s], b0, b1);
                }
#pragma unroll
            for (int nt = 0; nt < 8; nt++) {
                int gc = c * 128 + nb * 64 + nt * 8 + r * 2;
                float sn0 = snf[gc], sn1 = snf[gc + 1];
#pragma unroll
                for (int m = 0; m < 2; m++) {
                    upd(trk[m][0], fmaf(-2.f, acc[nt][m][0], sn0), gc);
                    upd(trk[m][0], fmaf(-2.f, acc[nt][m][1], sn1), gc + 1);
                    upd(trk[m][1], fmaf(-2.f, acc[nt][m][2], sn0), gc);
                    upd(trk[m][1], fmaf(-2.f, acc[nt][m][3], sn1), gc + 1);
                }
            }
        }
        __syncthreads();
    }

    // merge top-3 across the 4 lanes of each quad (rows are shared within a quad)
    const int pbase = p0 + w * 32;
#pragma unroll
    for (int m = 0; m < 2; m++)
#pragma unroll
        for (int h = 0; h < 2; h++) {
            Trk t = trk[m][h];
#pragma unroll
            for (int ofs = 1; ofs <= 2; ofs <<= 1) {
                float ov1 = __shfl_xor_sync(0xFFFFFFFFu, t.v1, ofs);
                int   oi1 = __shfl_xor_sync(0xFFFFFFFFu, t.i1, ofs);
                float ov2 = __shfl_xor_sync(0xFFFFFFFFu, t.v2, ofs);
                int   oi2 = __shfl_xor_sync(0xFFFFFFFFu, t.i2, ofs);
                float ov3 = __shfl_xor_sync(0xFFFFFFFFu, t.v3, ofs);
                upd(t, ov1, oi1);
                upd(t, ov2, oi2);               // ov3 can never enter top-2 here
                t.v3 = fminf(t.v3, ov3);
            }
            if (r == 0) {
                int pos = pbase + m * 16 + h * 8 + q;
                unsigned f2 = (__fsub_rn(t.v2, t.v1) <= MARGIN) ? 0x80000000u : 0u;
                g_top[pos] = make_uint2((unsigned)t.i1 | f2, (unsigned)t.i2);
                if (__fsub_rn(t.v3, t.v1) <= MARGIN) {
                    unsigned n = atomicAdd(&g_flagcnt, 1u);
                    g_flaglist[n] = pos;
                }
            }
        }
}

// ---------------- K4: finalize (exact top-2 rescore + scatter) ----------------
__global__ __launch_bounds__(256) void vq_finalize_kernel(const float* __restrict__ z,
                                                          const float* __restrict__ emb,
                                                          float* __restrict__ out) {
    int pos = blockIdx.x * 256 + threadIdx.x;
    uint2 t = g_top[pos];
    int i1 = (int)(t.x & 0x7FFFFFFFu), i2 = (int)t.y;
    int base = (pos >> 15) * (ED * SP) + (pos & (SP - 1));
    int idx = i1;
    if (t.x & 0x80000000u) {
        float xn = 0.f, d1 = 0.f, d2 = 0.f;
        const float* e1 = emb + i1 * ED;
        const float* e2 = emb + i2 * ED;
#pragma unroll
        for (int k = 0; k < ED; k++) {
            float x = z[base + k * SP];
            xn = __fadd_rn(xn, __fmul_rn(x, x));
            d1 = fmaf(x, e1[k], d1);
            d2 = fmaf(x, e2[k], d2);
        }
        float dd1 = __fsub_rn(__fadd_rn(xn, g_norms[i1]), __fmul_rn(2.0f, d1));
        float dd2 = __fsub_rn(__fadd_rn(xn, g_norms[i2]), __fmul_rn(2.0f, d2));
        if (dd2 < dd1 || (dd2 == dd1 && i2 < i1)) idx = i2;
    }
    const float4* er = (const float4*)(emb + idx * ED);
#pragma unroll
    for (int k = 0; k < ED / 4; k++) {
        float4 v = er[k];
        out[base + (4 * k + 0) * SP] = v.x;
        out[base + (4 * k + 1) * SP] = v.y;
        out[base + (4 * k + 2) * SP] = v.z;
        out[base + (4 * k + 3) * SP] = v.w;
    }
}

// ---------------- K5: full exact scan for flag3 positions (warp/position) ----------------
__global__ __launch_bounds__(128) void vq_fullscan_kernel(const float* __restrict__ z,
                                                          const float* __restrict__ emb,
                                                          float* __restrict__ out) {
    int w = (blockIdx.x * 128 + threadIdx.x) >> 5, lid = threadIdx.x & 31;
    int nw = gridDim.x * 4;
    unsigned cnt = g_flagcnt;
    for (unsigned f = w; f < cnt; f += nw) {
        int pos = g_flaglist[f];
        int base = (pos >> 15) * (ED * SP) + (pos & (SP - 1));
        float x[ED], xn = 0.f;
#pragma unroll
        for (int k = 0; k < ED; k++) {
            x[k] = z[base + k * SP];
            xn = __fadd_rn(xn, __fmul_rn(x[k], x[k]));
        }
        float best = 3.4e38f; int bi = EN;
        for (int c = lid; c < EN; c += 32) {
            const float* e = emb + c * ED;
            float dot = 0.f;
#pragma unroll
            for (int k = 0; k < ED; k++) dot = fmaf(x[k], e[k], dot);
            float d = __fsub_rn(__fadd_rn(xn, g_norms[c]), __fmul_rn(2.0f, dot));
            if (d < best) { best = d; bi = c; }
        }
        for (int o = 16; o; o >>= 1) {
            float ob = __shfl_down_sync(0xFFFFFFFFu, best, o);
            int   oi = __shfl_down_sync(0xFFFFFFFFu, bi, o);
            if (ob < best || (ob == best && oi < bi)) { best = ob; bi = oi; }
        }
        bi = __shfl_sync(0xFFFFFFFFu, bi, 0);
        for (int k = lid; k < ED; k += 32) out[base + k * SP] = emb[bi * ED + k];
    }
}

// ---------------- launcher ----------------
extern "C" void kernel_launch(void* const* d_in, const int* in_sizes, int n_in,
                              void* d_out, int out_size) {
    const float* z   = (const float*)d_in[0];
    const float* emb = (const float*)d_in[1];
    if (n_in >= 2 && in_sizes[0] == EN * ED && in_sizes[1] != EN * ED) {
        z = (const float*)d_in[1]; emb = (const float*)d_in[0];
    }
    float* out = (float*)d_out;

    cudaFuncSetAttribute(vq_gemm_kernel,
                         cudaFuncAttributeMaxDynamicSharedMemorySize, SMEM_BYTES);
    vq_norms_kernel<<<(EN + 255) / 256, 256>>>(emb);
    vq_ebuild_kernel<<<EN * 64 / 256, 256>>>(emb);
    vq_gemm_kernel<<<NCTA, 256, SMEM_BYTES>>>(z);
    vq_finalize_kernel<<<NPOS / 256, 256>>>(z, emb, out);
    vq_fullscan_kernel<<<296, 128>>>(z, emb, out);
}

// round 7
// speedup vs baseline: 1.2171x; 1.2171x over previous
#include <cuda_runtime.h>
#include <stdint.h>

#define EN    1024
#define ED    64
#define SP    32768
#define NPOS  131072
#define CTAP  256               // positions per CTA
#define NCTA  (NPOS / CTAP)     // 512
#define MARGIN 1e-4f

// smem byte offsets: norms 4KB | xs 64KB | e-chunk double buffer 2x16KB
#define B_SN  0
#define B_XS  4096
#define B_E0  69632
#define B_E1  86016
#define SMEM_BYTES 102400

__device__ float  g_norms[EN];
__device__ float2 g_epk[16 * 2048];   // [chunk][k2][code] fp32 dim-pairs
__device__ uint2    g_top[NPOS];
__device__ unsigned g_flagcnt;
__device__ unsigned g_flaglist[NPOS];

// ---------------- helpers ----------------
__device__ __forceinline__ unsigned sptr(const void* p) {
    return (unsigned)__cvta_generic_to_shared(p);
}
#define CP16(d, s)  asm volatile("cp.async.cg.shared.global [%0], [%1], 16;" :: "r"(d), "l"(s) : "memory")
#define CP_COMMIT() asm volatile("cp.async.commit_group;" ::: "memory")
#define CP_WAIT1()  asm volatile("cp.async.wait_group 1;" ::: "memory")
#define CP_WAIT0()  asm volatile("cp.async.wait_group 0;" ::: "memory")
#define FM(a, x, e) asm("fma.rn.f32x2 %0, %1, %2, %0;" : "+l"(a) : "l"(x), "l"(e))
#define LDS2U64(a, b, addr) asm("ld.shared.v2.u64 {%0,%1}, [%2];" : "=l"(a), "=l"(b) : "r"(addr))

// ---------------- K1: norms + flag reset ----------------
__global__ void vq_norms_kernel(const float* __restrict__ emb) {
    if (blockIdx.x == 0 && threadIdx.x == 0) g_flagcnt = 0;
    int j = blockIdx.x * blockDim.x + threadIdx.x;
    if (j < EN) {
        const float4* row = (const float4*)(emb + j * ED);
        float s = 0.f;
#pragma unroll
        for (int k = 0; k < ED / 4; k++) {
            float4 v = row[k];
            s += v.x * v.x + v.y * v.y + v.z * v.z + v.w * v.w;
        }
        g_norms[j] = s;
    }
}

// ---------------- K2: codebook -> k-pair-packed chunks [ch][k2][c] ----------------
__global__ __launch_bounds__(256) void vq_ebuild_kernel(const float* __restrict__ emb) {
    int idx = blockIdx.x * 256 + threadIdx.x;            // 0..32767
    int ch = idx >> 11, rem = idx & 2047, k2 = rem >> 6, c = rem & 63;
    int j = ch * 64 + c;
    g_epk[idx] = make_float2(emb[j * ED + 2 * k2], emb[j * ED + 2 * k2 + 1]);
}

// ---------------- K3: FFMA2 outer-product + top2/top3 shortlist ----------------
__global__ __launch_bounds__(256) void vq_gemm_kernel(const float* __restrict__ z) {
    extern __shared__ char sm[];
    const int tid = threadIdx.x, w = tid >> 5, l = tid & 31;
    const int pg = l & 7, cg = l >> 3;
    const unsigned sb = sptr(sm);

    // group0: all norms + e-chunk 0
    CP16(sb + B_SN + tid * 16, (const char*)g_norms + tid * 16);
    {
        const char* src = (const char*)g_epk;
#pragma unroll
        for (int i = 0; i < 4; i++)
            CP16(sb + B_E0 + (tid + i * 256) * 16, src + (tid + i * 256) * 16);
    }
    CP_COMMIT();

    // build xs[k2][p] = {x[p][2k2], x[p][2k2+1]} (coalesced gmem loads)
    const int p0 = blockIdx.x * CTAP;
    const float* zb = z + (p0 >> 15) * (ED * SP) + (p0 & (SP - 1));
#pragma unroll 4
    for (int k2 = 0; k2 < 32; k2++) {
        float f0 = zb[(2 * k2) * SP + tid];
        float f1 = zb[(2 * k2 + 1) * SP + tid];
        asm volatile("st.shared.v2.f32 [%0], {%1,%2};"
                     :: "r"(sb + B_XS + (k2 * 256 + tid) * 8), "f"(f0), "f"(f1) : "memory");
    }

    float tv1[4], tv2[4], tv3[4];
    int   ti1[4], ti2[4];
#pragma unroll
    for (int pp = 0; pp < 4; pp++) {
        tv1[pp] = tv2[pp] = tv3[pp] = 3.4e38f;
        ti1[pp] = ti2[pp] = 0;
    }
    const unsigned xbase = sb + B_XS + (w * 32 + 4 * pg) * 8;

#pragma unroll 1
    for (int ch = 0; ch < 16; ch++) {
        if (ch < 15) {
            const char* src = (const char*)(g_epk + (ch + 1) * 2048);
            unsigned eb = sb + (((ch + 1) & 1) ? B_E1 : B_E0);
#pragma unroll
            for (int i = 0; i < 4; i++)
                CP16(eb + (tid + i * 256) * 16, src + (tid + i * 256) * 16);
            CP_COMMIT();
            CP_WAIT1();
        } else {
            CP_WAIT0();
        }
        __syncthreads();
        const unsigned ebuf = sb + ((ch & 1) ? B_E1 : B_E0);

#pragma unroll 1
        for (int h = 0; h < 2; h++) {
            unsigned long long acc[32];
#pragma unroll
            for (int i = 0; i < 32; i++) acc[i] = 0ULL;
            unsigned xp = xbase;
            unsigned ep = ebuf + (h * 32 + cg * 8) * 8;
#pragma unroll 4
            for (int k2 = 0; k2 < 32; k2++) {
                unsigned long long xq[4], ee[8];
                LDS2U64(xq[0], xq[1], xp);
                LDS2U64(xq[2], xq[3], xp + 16);
                LDS2U64(ee[0], ee[1], ep);
                LDS2U64(ee[2], ee[3], ep + 16);
                LDS2U64(ee[4], ee[5], ep + 32);
                LDS2U64(ee[6], ee[7], ep + 48);
#pragma unroll
                for (int pp = 0; pp < 4; pp++)
#pragma unroll
                    for (int c = 0; c < 8; c++)
                        FM(acc[pp * 8 + c], xq[pp], ee[c]);
                xp += 2048;          // next k2 row of xs (256 u64)
                ep += 512;           // next k2 row of e  (64 u64)
            }
            // epilogue: d = ||e||^2 - 2*dot (exact fp32), track top-3
#pragma unroll
            for (int c = 0; c < 8; c++) {
                int gc = ch * 64 + h * 32 + cg * 8 + c;
                float sn;
                asm("ld.shared.f32 %0, [%1];" : "=f"(sn) : "r"(sb + B_SN + gc * 4));
#pragma unroll
                for (int pp = 0; pp < 4; pp++) {
                    float lo, hi;
                    asm("mov.b64 {%0,%1}, %2;" : "=f"(lo), "=f"(hi) : "l"(acc[pp * 8 + c]));
                    float d = fmaf(-2.f, lo + hi, sn);
                    if (d < tv1[pp]) { tv3[pp] = tv2[pp]; tv2[pp] = tv1[pp]; ti2[pp] = ti1[pp];
                                       tv1[pp] = d; ti1[pp] = gc; }
                    else if (d < tv2[pp]) { tv3[pp] = tv2[pp]; tv2[pp] = d; ti2[pp] = gc; }
                    else if (d < tv3[pp]) { tv3[pp] = d; }
                }
            }
        }
        __syncthreads();             // reads done before next prefetch overwrites
    }

    // merge across the 4 threads (cg=0..3) sharing each position group
#pragma unroll
    for (int pp = 0; pp < 4; pp++) {
        float v1 = tv1[pp], v2 = tv2[pp], v3 = tv3[pp];
        int   i1 = ti1[pp], i2 = ti2[pp];
#pragma unroll
        for (int ofs = 8; ofs <= 16; ofs <<= 1) {
            float ov1 = __shfl_xor_sync(~0u, v1, ofs);
            int   oi1 = __shfl_xor_sync(~0u, i1, ofs);
            float ov2 = __shfl_xor_sync(~0u, v2, ofs);
            int   oi2 = __shfl_xor_sync(~0u, i2, ofs);
            float ov3 = __shfl_xor_sync(~0u, v3, ofs);
            if (ov1 < v1) { v3 = v2; v2 = v1; i2 = i1; v1 = ov1; i1 = oi1; }
            else if (ov1 < v2) { v3 = v2; v2 = ov1; i2 = oi1; }
            else if (ov1 < v3) { v3 = ov1; }
            if (ov2 < v1) { v3 = v2; v2 = v1; i2 = i1; v1 = ov2; i1 = oi2; }
            else if (ov2 < v2) { v3 = v2; v2 = ov2; i2 = oi2; }
            else if (ov2 < v3) { v3 = ov2; }
            v3 = fminf(v3, ov3);
        }
        if (cg == 0) {
            int pos = p0 + w * 32 + 4 * pg + pp;
            unsigned f2 = (__fsub_rn(v2, v1) <= MARGIN) ? 0x80000000u : 0u;
            g_top[pos] = make_uint2((unsigned)i1 | f2, (unsigned)i2);
            if (__fsub_rn(v3, v1) <= MARGIN) {
                unsigned n = atomicAdd(&g_flagcnt, 1u);
                g_flaglist[n] = pos;
            }
        }
    }
}

// ---------------- K4: finalize (exact reference-rounded top-2 rescore + scatter) ----------------
__global__ __launch_bounds__(256) void vq_finalize_kernel(const float* __restrict__ z,
                                                          const float* __restrict__ emb,
                                                          float* __restrict__ out) {
    int pos = blockIdx.x * 256 + threadIdx.x;
    uint2 t = g_top[pos];
    int i1 = (int)(t.x & 0x7FFFFFFFu), i2 = (int)t.y;
    int base = (pos >> 15) * (ED * SP) + (pos & (SP - 1));
    int idx = i1;
    if (t.x & 0x80000000u) {
        float xn = 0.f, d1 = 0.f, d2 = 0.f;
        const float* e1 = emb + i1 * ED;
        const float* e2 = emb + i2 * ED;
#pragma unroll
        for (int k = 0; k < ED; k++) {
            float x = z[base + k * SP];
            xn = __fadd_rn(xn, __fmul_rn(x, x));
            d1 = fmaf(x, e1[k], d1);
            d2 = fmaf(x, e2[k], d2);
        }
        float dd1 = __fsub_rn(__fadd_rn(xn, g_norms[i1]), __fmul_rn(2.0f, d1));
        float dd2 = __fsub_rn(__fadd_rn(xn, g_norms[i2]), __fmul_rn(2.0f, d2));
        if (dd2 < dd1 || (dd2 == dd1 && i2 < i1)) idx = i2;
    }
    const float4* er = (const float4*)(emb + idx * ED);
#pragma unroll
    for (int k = 0; k < ED / 4; k++) {
        float4 v = er[k];
        out[base + (4 * k + 0) * SP] = v.x;
        out[base + (4 * k + 1) * SP] = v.y;
        out[base + (4 * k + 2) * SP] = v.z;
        out[base + (4 * k + 3) * SP] = v.w;
    }
}

// ---------------- K5: full exact scan for flag3 positions (warp/position) ----------------
__global__ __launch_bounds__(128) void vq_fullscan_kernel(const float* __restrict__ z,
                                                          const float* __restrict__ emb,
                                                          float* __restrict__ out) {
    int w = (blockIdx.x * 128 + threadIdx.x) >> 5, lid = threadIdx.x & 31;
    int nw = gridDim.x * 4;
    unsigned cnt = g_flagcnt;
    for (unsigned f = w; f < cnt; f += nw) {
        int pos = g_flaglist[f];
        int base = (pos >> 15) * (ED * SP) + (pos & (SP - 1));
        float x[ED], xn = 0.f;
#pragma unroll
        for (int k = 0; k < ED; k++) {
            x[k] = z[base + k * SP];
            xn = __fadd_rn(xn, __fmul_rn(x[k], x[k]));
        }
        float best = 3.4e38f; int bi = EN;
        for (int c = lid; c < EN; c += 32) {
            const float* e = emb + c * ED;
            float dot = 0.f;
#pragma unroll
            for (int k = 0; k < ED; k++) dot = fmaf(x[k], e[k], dot);
            float d = __fsub_rn(__fadd_rn(xn, g_norms[c]), __fmul_rn(2.0f, dot));
            if (d < best) { best = d; bi = c; }
        }
        for (int o = 16; o; o >>= 1) {
            float ob = __shfl_down_sync(0xFFFFFFFFu, best, o);
            int   oi = __shfl_down_sync(0xFFFFFFFFu, bi, o);
            if (ob < best || (ob == best && oi < bi)) { best = ob; bi = oi; }
        }
        bi = __shfl_sync(0xFFFFFFFFu, bi, 0);
        for (int k = lid; k < ED; k += 32) out[base + k * SP] = emb[bi * ED + k];
    }
}

// ---------------- launcher ----------------
extern "C" void kernel_launch(void* const* d_in, const int* in_sizes, int n_in,
                              void* d_out, int out_size) {
    const float* z   = (const float*)d_in[0];
    const float* emb = (const float*)d_in[1];
    if (n_in >= 2 && in_sizes[0] == EN * ED && in_sizes[1] != EN * ED) {
        z = (const float*)d_in[1]; emb = (const float*)d_in[0];
    }
    float* out = (float*)d_out;

    cudaFuncSetAttribute(vq_gemm_kernel,
                         cudaFuncAttributeMaxDynamicSharedMemorySize, SMEM_BYTES);
    vq_norms_kernel<<<(EN + 255) / 256, 256>>>(emb);
    vq_ebuild_kernel<<<128, 256>>>(emb);
    vq_gemm_kernel<<<NCTA, 256, SMEM_BYTES>>>(z);
    vq_finalize_kernel<<<NPOS / 256, 256>>>(z, emb, out);
    vq_fullscan_kernel<<<128, 128>>>(z, emb, out);
}

// round 8
// speedup vs baseline: 1.9340x; 1.5889x over previous
#include <cuda_runtime.h>
#include <stdint.h>

#define EMBED_NUM 1024
#define EMBED_DIM 64
#define SPATIAL   32768
#define NVEC      131072
#define CHUNK     128
#define THREADS   128
#define PPT       2

// dynamic smem layout (bytes): buf0 32768 | buf1 32768 | snorm0 512 | snorm1 512
#define SM_BUF(i)  ((i) * 32768)
#define SM_SN(i)   (65536 + (i) * 512)
#define SMEM_BYTES 66560

__device__ float g_norms[EMBED_NUM];

__device__ __forceinline__ unsigned sptr(const void* p) {
    return (unsigned)__cvta_generic_to_shared(p);
}
#define CP16(d, s)  asm volatile("cp.async.cg.shared.global [%0], [%1], 16;" :: "r"(d), "l"(s) : "memory")
#define CP_COMMIT() asm volatile("cp.async.commit_group;" ::: "memory")
#define CP_WAIT0()  asm volatile("cp.async.wait_group 0;" ::: "memory")
#define FM(a, x, e) asm("fma.rn.f32x2 %0, %1, %2, %0;" : "+l"(a) : "l"(x), "l"(e))

// --------------------------------------------------------------------------
__global__ void vq_norms_kernel(const float* __restrict__ emb) {
    int j = blockIdx.x * blockDim.x + threadIdx.x;
    if (j < EMBED_NUM) {
        const float4* row = reinterpret_cast<const float4*>(emb + j * EMBED_DIM);
        float s = 0.f;
#pragma unroll
        for (int k = 0; k < EMBED_DIM / 4; k++) {
            float4 v = row[k];
            s += v.x * v.x + v.y * v.y + v.z * v.z + v.w * v.w;
        }
        g_norms[j] = s;
    }
}

// --------------------------------------------------------------------------
// One thread = 2 positions (x register-resident, 128 regs), 4 codes per
// inner block (16 independent FFMA2 chains), cp.async double-buffered
// codebook chunks. Per-code arithmetic identical to the validated R3 kernel:
//   packed FFMA2 chains over q=0..15, dot = (t0+t1)+(t2+t3),
//   d = fsub_rn(fadd_rn(xnorm, ||e||^2), fmul_rn(2, dot)), ascending-j strict <.
// --------------------------------------------------------------------------
__global__ __launch_bounds__(THREADS, 2)
void vq_argmin_kernel(const float* __restrict__ z,
                      const float* __restrict__ emb,
                      float* __restrict__ out) {
    extern __shared__ char smraw[];
    const unsigned sb = sptr(smraw);

    const int p0 = blockIdx.x * (THREADS * PPT) + threadIdx.x;
    const int p1 = p0 + THREADS;
    const int b  = p0 >> 15;
    const int base0 = b * (EMBED_DIM * SPATIAL) + (p0 & (SPATIAL - 1));
    const int base1 = b * (EMBED_DIM * SPATIAL) + (p1 & (SPATIAL - 1));

    // prefetch chunk 0 (+norms) while we load x
    {
        const char* src = (const char*)(emb);          // chunk 0 = rows 0..127
        unsigned dst = sb + SM_BUF(0);
#pragma unroll
        for (int i = 0; i < 16; i++)
            CP16(dst + (threadIdx.x + i * 128) * 16, src + (threadIdx.x + i * 128) * 16);
        if (threadIdx.x < 32)
            CP16(sb + SM_SN(0) + threadIdx.x * 16, (const char*)g_norms + threadIdx.x * 16);
        CP_COMMIT();
    }

    // x for both positions -> packed f32x2 registers + xnorms (R3-identical)
    unsigned long long x0[EMBED_DIM / 2], x1[EMBED_DIM / 2];
    float xn0 = 0.f, xn1 = 0.f;
#pragma unroll
    for (int k = 0; k < EMBED_DIM; k += 2) {
        float a = z[base0 + k * SPATIAL];
        float c = z[base0 + (k + 1) * SPATIAL];
        xn0 = __fadd_rn(xn0, __fmul_rn(a, a));
        xn0 = __fadd_rn(xn0, __fmul_rn(c, c));
        asm("mov.b64 %0, {%1, %2};" : "=l"(x0[k >> 1]) : "f"(a), "f"(c));
        float d = z[base1 + k * SPATIAL];
        float e = z[base1 + (k + 1) * SPATIAL];
        xn1 = __fadd_rn(xn1, __fmul_rn(d, d));
        xn1 = __fadd_rn(xn1, __fmul_rn(e, e));
        asm("mov.b64 %0, {%1, %2};" : "=l"(x1[k >> 1]) : "f"(d), "f"(e));
    }

    float best0 = 3.4e38f, best1 = 3.4e38f;
    int   bi0 = 0, bi1 = 0;

    CP_WAIT0();
    __syncthreads();

#pragma unroll 1
    for (int c = 0; c < EMBED_NUM / CHUNK; c++) {
        if (c < EMBED_NUM / CHUNK - 1) {               // prefetch next chunk
            const char* src = (const char*)(emb + (c + 1) * CHUNK * EMBED_DIM);
            unsigned dst = sb + SM_BUF((c + 1) & 1);
#pragma unroll
            for (int i = 0; i < 16; i++)
                CP16(dst + (threadIdx.x + i * 128) * 16, src + (threadIdx.x + i * 128) * 16);
            if (threadIdx.x < 32)
                CP16(sb + SM_SN((c + 1) & 1) + threadIdx.x * 16,
                     (const char*)(g_norms + (c + 1) * CHUNK) + threadIdx.x * 16);
            CP_COMMIT();
        }
        const float4* se   = (const float4*)(smraw + SM_BUF(c & 1));
        const float*  snrm = (const float*) (smraw + SM_SN(c & 1));
        const int cbase = c * CHUNK;

#pragma unroll 1
        for (int j = 0; j < CHUNK; j += 4) {
            const ulonglong2* e0 = (const ulonglong2*)(se + (j + 0) * 16);
            const ulonglong2* e1 = (const ulonglong2*)(se + (j + 1) * 16);
            const ulonglong2* e2 = (const ulonglong2*)(se + (j + 2) * 16);
            const ulonglong2* e3 = (const ulonglong2*)(se + (j + 3) * 16);
            unsigned long long a0L = 0, a0H = 0, a1L = 0, a1H = 0;   // pos0, codes j..j+3
            unsigned long long a2L = 0, a2H = 0, a3L = 0, a3H = 0;
            unsigned long long b0L = 0, b0H = 0, b1L = 0, b1H = 0;   // pos1
            unsigned long long b2L = 0, b2H = 0, b3L = 0, b3H = 0;
#pragma unroll
            for (int q = 0; q < 16; q++) {
                ulonglong2 v0 = e0[q];                 // LDS.128 broadcast
                ulonglong2 v1 = e1[q];
                ulonglong2 v2 = e2[q];
                ulonglong2 v3 = e3[q];
                unsigned long long xa0 = x0[2 * q], xa1 = x0[2 * q + 1];
                unsigned long long xb0 = x1[2 * q], xb1 = x1[2 * q + 1];
                FM(a0L, xa0, v0.x); FM(a0H, xa1, v0.y);
                FM(a1L, xa0, v1.x); FM(a1H, xa1, v1.y);
                FM(a2L, xa0, v2.x); FM(a2H, xa1, v2.y);
                FM(a3L, xa0, v3.x); FM(a3H, xa1, v3.y);
                FM(b0L, xb0, v0.x); FM(b0H, xb1, v0.y);
                FM(b1L, xb0, v1.x); FM(b1H, xb1, v1.y);
                FM(b2L, xb0, v2.x); FM(b2H, xb1, v2.y);
                FM(b3L, xb0, v3.x); FM(b3H, xb1, v3.y);
            }
            float en0 = snrm[j], en1 = snrm[j + 1], en2 = snrm[j + 2], en3 = snrm[j + 3];
            float t0, t1, t2, t3, dot, d;

#define EPI(POS_XN, POS_BEST, POS_BI, AL, AH, EN, COL)                                 \
            asm("mov.b64 {%0,%1}, %2;" : "=f"(t0), "=f"(t1) : "l"(AL));                \
            asm("mov.b64 {%0,%1}, %2;" : "=f"(t2), "=f"(t3) : "l"(AH));                \
            dot = (t0 + t1) + (t2 + t3);                                               \
            d = __fsub_rn(__fadd_rn(POS_XN, EN), __fmul_rn(2.0f, dot));                \
            if (d < POS_BEST) { POS_BEST = d; POS_BI = (COL); }

            EPI(xn0, best0, bi0, a0L, a0H, en0, cbase + j)
            EPI(xn0, best0, bi0, a1L, a1H, en1, cbase + j + 1)
            EPI(xn0, best0, bi0, a2L, a2H, en2, cbase + j + 2)
            EPI(xn0, best0, bi0, a3L, a3H, en3, cbase + j + 3)
            EPI(xn1, best1, bi1, b0L, b0H, en0, cbase + j)
            EPI(xn1, best1, bi1, b1L, b1H, en1, cbase + j + 1)
            EPI(xn1, best1, bi1, b2L, b2H, en2, cbase + j + 2)
            EPI(xn1, best1, bi1, b3L, b3H, en3, cbase + j + 3)
#undef EPI
        }
        if (c < EMBED_NUM / CHUNK - 1) CP_WAIT0();
        __syncthreads();
    }

    // gather winners (L2-resident rows) + channel-strided scatter
    const float4* er0 = (const float4*)(emb + bi0 * EMBED_DIM);
    const float4* er1 = (const float4*)(emb + bi1 * EMBED_DIM);
#pragma unroll
    for (int k = 0; k < EMBED_DIM / 4; k++) {
        float4 v = er0[k];
        out[base0 + (4 * k + 0) * SPATIAL] = v.x;
        out[base0 + (4 * k + 1) * SPATIAL] = v.y;
        out[base0 + (4 * k + 2) * SPATIAL] = v.z;
        out[base0 + (4 * k + 3) * SPATIAL] = v.w;
        float4 w = er1[k];
        out[base1 + (4 * k + 0) * SPATIAL] = w.x;
        out[base1 + (4 * k + 1) * SPATIAL] = w.y;
        out[base1 + (4 * k + 2) * SPATIAL] = w.z;
        out[base1 + (4 * k + 3) * SPATIAL] = w.w;
    }
}

// --------------------------------------------------------------------------
extern "C" void kernel_launch(void* const* d_in, const int* in_sizes, int n_in,
                              void* d_out, int out_size) {
    const float* z   = (const float*)d_in[0];
    const float* emb = (const float*)d_in[1];
    if (n_in >= 2 && in_sizes[0] == EMBED_NUM * EMBED_DIM &&
        in_sizes[1] != EMBED_NUM * EMBED_DIM) {
        z   = (const float*)d_in[1];
        emb = (const float*)d_in[0];
    }
    float* out = (float*)d_out;

    cudaFuncSetAttribute(vq_argmin_kernel,
                         cudaFuncAttributeMaxDynamicSharedMemorySize, SMEM_BYTES);
    vq_norms_kernel<<<(EMBED_NUM + 255) / 256, 256>>>(emb);
    vq_argmin_kernel<<<NVEC / (THREADS * PPT), THREADS, SMEM_BYTES>>>(z, emb, out);
}